// round 7
// baseline (speedup 1.0000x reference)
#include <cuda_runtime.h>
#include <cuda_fp16.h>
#include <cstdint>

// Problem dims (fixed by setup_inputs)
#define N_ROWS 16384
#define D_DIM  768
#define P_DIM  2048
#define C_DIM  1000
#define C_PAD  1024

// Scratch (allocation-free: __device__ globals)
__device__ __half g_hn[(size_t)N_ROWS * D_DIM];   // normalized h, fp16
__device__ __half g_pn[(size_t)P_DIM  * D_DIM];   // normalized prototypes, fp16
__device__ __half g_act[(size_t)N_ROWS * P_DIM];  // activations, fp16
__device__ __half g_pct[(size_t)C_PAD  * P_DIM];  // prototype_class transposed+padded

// ---------------------------------------------------------------------------
// Row L2 normalize: one block per row, fp32 in -> fp16 out.
// Handles both h (rows 0..N_ROWS-1) and prototypes (rows N_ROWS..) in one grid.
// ---------------------------------------------------------------------------
__global__ void normalize_rows_kernel(const float* __restrict__ xh,
                                      const float* __restrict__ xp) {
    int row = blockIdx.x;
    const float* xr;
    __half* yr;
    if (row < N_ROWS) {
        xr = xh + (size_t)row * D_DIM;
        yr = g_hn + (size_t)row * D_DIM;
    } else {
        xr = xp + (size_t)(row - N_ROWS) * D_DIM;
        yr = g_pn + (size_t)(row - N_ROWS) * D_DIM;
    }
    float ss = 0.f;
    for (int i = threadIdx.x; i < D_DIM; i += blockDim.x) {
        float v = xr[i];
        ss += v * v;
    }
    #pragma unroll
    for (int o = 16; o; o >>= 1) ss += __shfl_xor_sync(0xffffffff, ss, o);
    __shared__ float wsum[8];
    int w = threadIdx.x >> 5, l = threadIdx.x & 31;
    if (l == 0) wsum[w] = ss;
    __syncthreads();
    if (w == 0) {
        float v = (l < (int)(blockDim.x >> 5)) ? wsum[l] : 0.f;
        #pragma unroll
        for (int o = 4; o; o >>= 1) v += __shfl_xor_sync(0xffffffff, v, o);
        if (l == 0) wsum[0] = v;
    }
    __syncthreads();
    float inv = 1.0f / fmaxf(sqrtf(wsum[0]), 1e-12f);
    for (int i = threadIdx.x; i < D_DIM; i += blockDim.x)
        yr[i] = __float2half(xr[i] * inv);
}

// ---------------------------------------------------------------------------
// Transpose prototype_class [P, C] fp32 -> g_pct [C_PAD, P] fp16, zero-padded
// ---------------------------------------------------------------------------
__global__ void transpose_pc_kernel(const float* __restrict__ pc) {
    __shared__ float tile[32][33];
    int p0 = blockIdx.x * 32, c0 = blockIdx.y * 32;
    int tx = threadIdx.x, ty = threadIdx.y;   // block (32, 8)
    #pragma unroll
    for (int j = 0; j < 32; j += 8) {
        int p = p0 + ty + j, c = c0 + tx;
        tile[ty + j][tx] = (c < C_DIM) ? pc[(size_t)p * C_DIM + c] : 0.f;
    }
    __syncthreads();
    #pragma unroll
    for (int j = 0; j < 32; j += 8) {
        int c = c0 + ty + j, p = p0 + tx;
        g_pct[(size_t)c * P_DIM + p] = __float2half(tile[tx][ty + j]);
    }
}

// ---------------------------------------------------------------------------
// Shared GEMM scaffolding: CTA tile 128x128x32, 128 threads (2x2 warps),
// warp tile 64x64, 4-stage cp.async, 2 CTAs/SM.
// ---------------------------------------------------------------------------
#define PADK   40
#define STAGES 4
#define GEMM_SMEM_BYTES (STAGES * 2 * 128 * PADK * sizeof(__half))  // 81920

__device__ __forceinline__ uint32_t smem_u32(const void* p) {
    return (uint32_t)__cvta_generic_to_shared(p);
}

#define LOAD_TILE(kt, s)                                                      \
    do {                                                                      \
        const __half* ga = A + (size_t)m0 * KDIM + (kt) * 32;                 \
        const __half* gb = B + (size_t)n0 * KDIM + (kt) * 32;                 \
        __half* sa = sm + (size_t)(s) * 2 * 128 * PADK;                       \
        __half* sb = sa + 128 * PADK;                                         \
        _Pragma("unroll")                                                     \
        for (int i = 0; i < 4; ++i) {                                         \
            int l = tid + i * 128;                                            \
            int row = l >> 2, ch = l & 3;                                     \
            asm volatile("cp.async.cg.shared.global [%0], [%1], 16;\n"        \
                :: "r"(smem_u32(sa + row * PADK + ch * 8)),                   \
                   "l"(ga + (size_t)row * KDIM + ch * 8));                    \
            asm volatile("cp.async.cg.shared.global [%0], [%1], 16;\n"        \
                :: "r"(smem_u32(sb + row * PADK + ch * 8)),                   \
                   "l"(gb + (size_t)row * KDIM + ch * 8));                    \
        }                                                                     \
    } while (0)

#define LDSM_A(r, sa, f, ks)                                                  \
    do {                                                                      \
        int row_ = wm * 64 + (f) * 16 + (lane & 15);                          \
        int col_ = (ks) * 16 + (lane >> 4) * 8;                               \
        asm volatile(                                                         \
            "ldmatrix.sync.aligned.m8n8.x4.shared.b16 {%0,%1,%2,%3}, [%4];\n" \
            : "=r"((r)[0]), "=r"((r)[1]), "=r"((r)[2]), "=r"((r)[3])          \
            : "r"(smem_u32((sa) + row_ * PADK + col_)));                      \
    } while (0)

#define LDSM_B(r, sb, p, ks)                                                  \
    do {                                                                      \
        int row_ = wn * 64 + (p) * 16 + (lane & 7) + ((lane >> 4) << 3);      \
        int col_ = (ks) * 16 + ((lane >> 3) & 1) * 8;                         \
        asm volatile(                                                         \
            "ldmatrix.sync.aligned.m8n8.x4.shared.b16 {%0,%1,%2,%3}, [%4];\n" \
            : "=r"((r)[0]), "=r"((r)[1]), "=r"((r)[2]), "=r"((r)[3])          \
            : "r"(smem_u32((sb) + row_ * PADK + col_)));                      \
    } while (0)

// ---------------------------------------------------------------------------
// GEMM1 kernel: f16 ACCUMULATORS + fused dist/exp epilogue.
// act[N,P] fp16 = exp(-tau * sqrt(max(2-2*(A row . B row), 0)))
// ---------------------------------------------------------------------------
__global__ void __launch_bounds__(128, 2) gemm_act_f16acc_kernel(
    const __half* __restrict__ A, const __half* __restrict__ B,
    __half* __restrict__ outH, const float* __restrict__ tempPtr)
{
    constexpr int KDIM = D_DIM;
    extern __shared__ __half sm[];
    const int tid  = threadIdx.x;
    const int warp = tid >> 5, lane = tid & 31;
    const int wm = warp >> 1, wn = warp & 1;
    const int m0 = blockIdx.y * 128, n0 = blockIdx.x * 128;

    uint32_t acc[4][8][2];   // f16x2 accumulators
    #pragma unroll
    for (int f = 0; f < 4; ++f)
        #pragma unroll
        for (int n = 0; n < 8; ++n) { acc[f][n][0] = 0u; acc[f][n][1] = 0u; }

    const int KT = KDIM / 32;

    #pragma unroll
    for (int s = 0; s < STAGES - 1; ++s) {
        LOAD_TILE(s, s);
        asm volatile("cp.async.commit_group;\n");
    }

    for (int kt = 0; kt < KT; ++kt) {
        asm volatile("cp.async.wait_group %0;\n" :: "n"(STAGES - 2));
        __syncthreads();
        const int cur = kt % STAGES;
        const int nxt = kt + STAGES - 1;
        if (nxt < KT) LOAD_TILE(nxt, nxt % STAGES);
        asm volatile("cp.async.commit_group;\n");

        const __half* sa = sm + (size_t)cur * 2 * 128 * PADK;
        const __half* sb = sa + 128 * PADK;
        #pragma unroll
        for (int ks = 0; ks < 2; ++ks) {
            uint32_t a[4][4], b[4][4];
            #pragma unroll
            for (int f = 0; f < 4; ++f) LDSM_A(a[f], sa, f, ks);
            #pragma unroll
            for (int p = 0; p < 4; ++p) LDSM_B(b[p], sb, p, ks);
            #pragma unroll
            for (int f = 0; f < 4; ++f)
                #pragma unroll
                for (int nf = 0; nf < 8; ++nf) {
                    uint32_t b0 = b[nf >> 1][(nf & 1) * 2 + 0];
                    uint32_t b1 = b[nf >> 1][(nf & 1) * 2 + 1];
                    uint32_t* c = acc[f][nf];
                    asm volatile(
                        "mma.sync.aligned.m16n8k16.row.col.f16.f16.f16.f16 "
                        "{%0,%1},{%2,%3,%4,%5},{%6,%7},{%0,%1};\n"
                        : "+r"(c[0]), "+r"(c[1])
                        : "r"(a[f][0]), "r"(a[f][1]), "r"(a[f][2]), "r"(a[f][3]),
                          "r"(b0), "r"(b1));
                }
        }
    }

    // Epilogue: acc reg0 = {c0,c1} at (row, col..col+1); reg1 at row+8.
    float t = __ldg(tempPtr);
    float tau = (t > 20.f) ? t : log1pf(expf(t));   // softplus
    #pragma unroll
    for (int f = 0; f < 4; ++f)
        #pragma unroll
        for (int nf = 0; nf < 8; ++nf) {
            int row = m0 + wm * 64 + f * 16 + (lane >> 2);
            int col = n0 + wn * 64 + nf * 8 + (lane & 3) * 2;
            #pragma unroll
            for (int hh = 0; hh < 2; ++hh) {
                int r = row + hh * 8;
                float2 d = __half22float2(*(__half2*)&acc[f][nf][hh]);
                float a0 = __expf(-tau * sqrtf(fmaxf(2.f - 2.f * d.x, 0.f)));
                float a1 = __expf(-tau * sqrtf(fmaxf(2.f - 2.f * d.y, 0.f)));
                *(__half2*)(outH + (size_t)r * P_DIM + col) =
                    __floats2half2_rn(a0, a1);
            }
        }
}

// ---------------------------------------------------------------------------
// GEMM2 kernel: fp32 accumulators, plain store to [N, C_DIM].
// ---------------------------------------------------------------------------
__global__ void __launch_bounds__(128, 2) gemm_f32acc_kernel(
    const __half* __restrict__ A, const __half* __restrict__ B,
    float* __restrict__ outF)
{
    constexpr int KDIM = P_DIM;
    extern __shared__ __half sm[];
    const int tid  = threadIdx.x;
    const int warp = tid >> 5, lane = tid & 31;
    const int wm = warp >> 1, wn = warp & 1;
    const int m0 = blockIdx.y * 128, n0 = blockIdx.x * 128;

    float acc[4][8][4];
    #pragma unroll
    for (int f = 0; f < 4; ++f)
        #pragma unroll
        for (int n = 0; n < 8; ++n)
            #pragma unroll
            for (int k = 0; k < 4; ++k) acc[f][n][k] = 0.f;

    const int KT = KDIM / 32;

    #pragma unroll
    for (int s = 0; s < STAGES - 1; ++s) {
        LOAD_TILE(s, s);
        asm volatile("cp.async.commit_group;\n");
    }

    for (int kt = 0; kt < KT; ++kt) {
        asm volatile("cp.async.wait_group %0;\n" :: "n"(STAGES - 2));
        __syncthreads();
        const int cur = kt % STAGES;
        const int nxt = kt + STAGES - 1;
        if (nxt < KT) LOAD_TILE(nxt, nxt % STAGES);
        asm volatile("cp.async.commit_group;\n");

        const __half* sa = sm + (size_t)cur * 2 * 128 * PADK;
        const __half* sb = sa + 128 * PADK;
        #pragma unroll
        for (int ks = 0; ks < 2; ++ks) {
            uint32_t a[4][4], b[4][4];
            #pragma unroll
            for (int f = 0; f < 4; ++f) LDSM_A(a[f], sa, f, ks);
            #pragma unroll
            for (int p = 0; p < 4; ++p) LDSM_B(b[p], sb, p, ks);
            #pragma unroll
            for (int f = 0; f < 4; ++f)
                #pragma unroll
                for (int nf = 0; nf < 8; ++nf) {
                    uint32_t b0 = b[nf >> 1][(nf & 1) * 2 + 0];
                    uint32_t b1 = b[nf >> 1][(nf & 1) * 2 + 1];
                    float* c = acc[f][nf];
                    asm volatile(
                        "mma.sync.aligned.m16n8k16.row.col.f32.f16.f16.f32 "
                        "{%0,%1,%2,%3},{%4,%5,%6,%7},{%8,%9},{%0,%1,%2,%3};\n"
                        : "+f"(c[0]), "+f"(c[1]), "+f"(c[2]), "+f"(c[3])
                        : "r"(a[f][0]), "r"(a[f][1]), "r"(a[f][2]), "r"(a[f][3]),
                          "r"(b0), "r"(b1));
                }
        }
    }

    #pragma unroll
    for (int f = 0; f < 4; ++f)
        #pragma unroll
        for (int nf = 0; nf < 8; ++nf) {
            int row = m0 + wm * 64 + f * 16 + (lane >> 2);
            int col = n0 + wn * 64 + nf * 8 + (lane & 3) * 2;
            if (col < C_DIM) {   // even cols; pair never straddles C_DIM
                #pragma unroll
                for (int hh = 0; hh < 2; ++hh) {
                    int r = row + hh * 8;
                    float2 v = make_float2(acc[f][nf][hh * 2 + 0],
                                           acc[f][nf][hh * 2 + 1]);
                    *(float2*)(outF + (size_t)r * C_DIM + col) = v;
                }
            }
        }
}

// ---------------------------------------------------------------------------
// kernel_launch: 4 launches, all graph-capturable, no allocations.
// ---------------------------------------------------------------------------
extern "C" void kernel_launch(void* const* d_in, const int* in_sizes, int n_in,
                              void* d_out, int out_size) {
    const float* h    = (const float*)d_in[0];
    const float* prot = (const float*)d_in[1];
    const float* pc   = (const float*)d_in[2];
    const float* temp = (const float*)d_in[3];
    float* out = (float*)d_out;

    __half *hn = nullptr, *pn = nullptr, *act = nullptr, *pct = nullptr;
    cudaGetSymbolAddress((void**)&hn,  g_hn);
    cudaGetSymbolAddress((void**)&pn,  g_pn);
    cudaGetSymbolAddress((void**)&act, g_act);
    cudaGetSymbolAddress((void**)&pct, g_pct);

    cudaFuncSetAttribute(gemm_act_f16acc_kernel,
                         cudaFuncAttributeMaxDynamicSharedMemorySize,
                         (int)GEMM_SMEM_BYTES);
    cudaFuncSetAttribute(gemm_f32acc_kernel,
                         cudaFuncAttributeMaxDynamicSharedMemorySize,
                         (int)GEMM_SMEM_BYTES);

    // 1) normalize h and prototypes -> fp16 (single launch)
    normalize_rows_kernel<<<N_ROWS + P_DIM, 256>>>(h, prot);
    // 2) transpose + pad prototype_class -> fp16 [C_PAD, P]
    transpose_pc_kernel<<<dim3(P_DIM / 32, C_PAD / 32), dim3(32, 8)>>>(pc);
    // 3) GEMM1 (f16 accum) + dist/exp epilogue -> activations fp16 [N, P]
    gemm_act_f16acc_kernel
        <<<dim3(P_DIM / 128, N_ROWS / 128), 128, GEMM_SMEM_BYTES>>>(
            hn, pn, act, temp);
    // 4) GEMM2 (fp32 accum) -> logits fp32 [N, C]
    gemm_f32acc_kernel
        <<<dim3(C_PAD / 128, N_ROWS / 128), 128, GEMM_SMEM_BYTES>>>(
            act, pct, out);
}

// round 8
// speedup vs baseline: 1.1365x; 1.1365x over previous
#include <cuda_runtime.h>
#include <cuda_fp16.h>
#include <cstdint>

// Problem dims (fixed by setup_inputs)
#define N_ROWS 16384
#define D_DIM  768
#define P_DIM  2048
#define C_DIM  1000
#define C_PAD  1024

// Scratch (allocation-free: __device__ globals)
__device__ __half g_hn[(size_t)N_ROWS * D_DIM];   // normalized h, fp16
__device__ __half g_pn[(size_t)P_DIM  * D_DIM];   // normalized prototypes, fp16
__device__ __half g_act[(size_t)N_ROWS * P_DIM];  // activations, fp16
__device__ __half g_pct[(size_t)C_PAD  * P_DIM];  // prototype_class transposed+padded

// ---------------------------------------------------------------------------
// Row L2 normalize (vectorized): one block per row, fp32 in -> fp16 out.
// Rows [0, N_ROWS) from xh -> g_hn; rows [N_ROWS, N_ROWS+P_DIM) from xp -> g_pn.
// D_DIM = 768 = 192 float4; 256 threads, threads 0..191 active per row.
// ---------------------------------------------------------------------------
__global__ void normalize_rows_kernel(const float* __restrict__ xh,
                                      const float* __restrict__ xp) {
    int row = blockIdx.x;
    const float* xr;
    __half* yr;
    if (row < N_ROWS) {
        xr = xh + (size_t)row * D_DIM;
        yr = g_hn + (size_t)row * D_DIM;
    } else {
        xr = xp + (size_t)(row - N_ROWS) * D_DIM;
        yr = g_pn + (size_t)(row - N_ROWS) * D_DIM;
    }
    int tid = threadIdx.x;
    float4 v = make_float4(0.f, 0.f, 0.f, 0.f);
    if (tid < 192) v = ((const float4*)xr)[tid];
    float ss = v.x * v.x + v.y * v.y + v.z * v.z + v.w * v.w;
    #pragma unroll
    for (int o = 16; o; o >>= 1) ss += __shfl_xor_sync(0xffffffff, ss, o);
    __shared__ float wsum[8];
    int w = tid >> 5, l = tid & 31;
    if (l == 0) wsum[w] = ss;
    __syncthreads();
    if (w == 0) {
        float s = (l < 8) ? wsum[l] : 0.f;
        #pragma unroll
        for (int o = 4; o; o >>= 1) s += __shfl_xor_sync(0xffffffff, s, o);
        if (l == 0) wsum[0] = s;
    }
    __syncthreads();
    float inv = 1.0f / fmaxf(sqrtf(wsum[0]), 1e-12f);
    if (tid < 192) {
        __half2 h0 = __floats2half2_rn(v.x * inv, v.y * inv);
        __half2 h1 = __floats2half2_rn(v.z * inv, v.w * inv);
        uint2 pack;
        pack.x = *(uint32_t*)&h0;
        pack.y = *(uint32_t*)&h1;
        ((uint2*)yr)[tid] = pack;
    }
}

// ---------------------------------------------------------------------------
// Transpose prototype_class [P, C] fp32 -> g_pct [C_PAD, P] fp16, zero-padded
// ---------------------------------------------------------------------------
__global__ void transpose_pc_kernel(const float* __restrict__ pc) {
    __shared__ float tile[32][33];
    int p0 = blockIdx.x * 32, c0 = blockIdx.y * 32;
    int tx = threadIdx.x, ty = threadIdx.y;   // block (32, 8)
    #pragma unroll
    for (int j = 0; j < 32; j += 8) {
        int p = p0 + ty + j, c = c0 + tx;
        tile[ty + j][tx] = (c < C_DIM) ? pc[(size_t)p * C_DIM + c] : 0.f;
    }
    __syncthreads();
    #pragma unroll
    for (int j = 0; j < 32; j += 8) {
        int c = c0 + ty + j, p = p0 + tx;
        g_pct[(size_t)c * P_DIM + p] = __float2half(tile[tx][ty + j]);
    }
}

// ---------------------------------------------------------------------------
// Shared GEMM scaffolding: CTA tile 128x128x32, 128 threads (2x2 warps),
// warp tile 64x64, 4-stage cp.async, 2 CTAs/SM, f32 accumulators.
// ---------------------------------------------------------------------------
#define PADK   40
#define STAGES 4
#define GEMM_SMEM_BYTES (STAGES * 2 * 128 * PADK * sizeof(__half))  // 81920

__device__ __forceinline__ uint32_t smem_u32(const void* p) {
    return (uint32_t)__cvta_generic_to_shared(p);
}

#define LOAD_TILE(kt, s)                                                      \
    do {                                                                      \
        const __half* ga = A + (size_t)m0 * KDIM + (kt) * 32;                 \
        const __half* gb = B + (size_t)n0 * KDIM + (kt) * 32;                 \
        __half* sa = sm + (size_t)(s) * 2 * 128 * PADK;                       \
        __half* sb = sa + 128 * PADK;                                         \
        _Pragma("unroll")                                                     \
        for (int i = 0; i < 4; ++i) {                                         \
            int l = tid + i * 128;                                            \
            int row = l >> 2, ch = l & 3;                                     \
            asm volatile("cp.async.cg.shared.global [%0], [%1], 16;\n"        \
                :: "r"(smem_u32(sa + row * PADK + ch * 8)),                   \
                   "l"(ga + (size_t)row * KDIM + ch * 8));                    \
            asm volatile("cp.async.cg.shared.global [%0], [%1], 16;\n"        \
                :: "r"(smem_u32(sb + row * PADK + ch * 8)),                   \
                   "l"(gb + (size_t)row * KDIM + ch * 8));                    \
        }                                                                     \
    } while (0)

#define LDSM_A(r, sa, f, ks)                                                  \
    do {                                                                      \
        int row_ = wm * 64 + (f) * 16 + (lane & 15);                          \
        int col_ = (ks) * 16 + (lane >> 4) * 8;                               \
        asm volatile(                                                         \
            "ldmatrix.sync.aligned.m8n8.x4.shared.b16 {%0,%1,%2,%3}, [%4];\n" \
            : "=r"((r)[0]), "=r"((r)[1]), "=r"((r)[2]), "=r"((r)[3])          \
            : "r"(smem_u32((sa) + row_ * PADK + col_)));                      \
    } while (0)

#define LDSM_B(r, sb, p, ks)                                                  \
    do {                                                                      \
        int row_ = wn * 64 + (p) * 16 + (lane & 7) + ((lane >> 4) << 3);      \
        int col_ = (ks) * 16 + ((lane >> 3) & 1) * 8;                         \
        asm volatile(                                                         \
            "ldmatrix.sync.aligned.m8n8.x4.shared.b16 {%0,%1,%2,%3}, [%4];\n" \
            : "=r"((r)[0]), "=r"((r)[1]), "=r"((r)[2]), "=r"((r)[3])          \
            : "r"(smem_u32((sb) + row_ * PADK + col_)));                      \
    } while (0)

#define HMMA_F32(c, a4, b0, b1)                                               \
    asm volatile(                                                             \
        "mma.sync.aligned.m16n8k16.row.col.f32.f16.f16.f32 "                  \
        "{%0,%1,%2,%3},{%4,%5,%6,%7},{%8,%9},{%0,%1,%2,%3};\n"                \
        : "+f"((c)[0]), "+f"((c)[1]), "+f"((c)[2]), "+f"((c)[3])              \
        : "r"((a4)[0]), "r"((a4)[1]), "r"((a4)[2]), "r"((a4)[3]),             \
          "r"(b0), "r"(b1))

// Mainloop over K (assumes acc zeroed, runs prologue; leaves cp.async drained)
#define GEMM_MAINLOOP(KDIM_)                                                  \
    do {                                                                      \
        constexpr int KDIM = (KDIM_);                                         \
        constexpr int KT = KDIM / 32;                                         \
        _Pragma("unroll")                                                     \
        for (int s = 0; s < STAGES - 1; ++s) {                                \
            LOAD_TILE(s, s);                                                  \
            asm volatile("cp.async.commit_group;\n");                         \
        }                                                                     \
        for (int kt = 0; kt < KT; ++kt) {                                     \
            asm volatile("cp.async.wait_group %0;\n" :: "n"(STAGES - 2));     \
            __syncthreads();                                                  \
            const int cur = kt % STAGES;                                      \
            const int nxt = kt + STAGES - 1;                                  \
            if (nxt < KT) LOAD_TILE(nxt, nxt % STAGES);                       \
            asm volatile("cp.async.commit_group;\n");                         \
            const __half* sa = sm + (size_t)cur * 2 * 128 * PADK;             \
            const __half* sb = sa + 128 * PADK;                               \
            _Pragma("unroll")                                                 \
            for (int ks = 0; ks < 2; ++ks) {                                  \
                uint32_t a[4][4], b[4][4];                                    \
                _Pragma("unroll")                                             \
                for (int f = 0; f < 4; ++f) LDSM_A(a[f], sa, f, ks);          \
                _Pragma("unroll")                                             \
                for (int p = 0; p < 4; ++p) LDSM_B(b[p], sb, p, ks);          \
                _Pragma("unroll")                                             \
                for (int f = 0; f < 4; ++f)                                   \
                    _Pragma("unroll")                                         \
                    for (int nf = 0; nf < 8; ++nf)                            \
                        HMMA_F32(acc[f][nf], a[f],                            \
                                 b[nf >> 1][(nf & 1) * 2 + 0],                \
                                 b[nf >> 1][(nf & 1) * 2 + 1]);               \
            }                                                                 \
        }                                                                     \
        asm volatile("cp.async.wait_group 0;\n");                             \
        __syncthreads();                                                      \
    } while (0)

// ---------------------------------------------------------------------------
// GEMM1: act[N,P] fp16 = exp(-tau*sqrt(max(2-2*(hn . pn), 0))), f32 accum.
// Grid 2048 CTAs (6.9 waves) — no persistence needed.
// ---------------------------------------------------------------------------
__global__ void __launch_bounds__(128, 2) gemm_act_kernel(
    const __half* __restrict__ A, const __half* __restrict__ B,
    __half* __restrict__ outH, const float* __restrict__ tempPtr)
{
    extern __shared__ __half sm[];
    const int tid  = threadIdx.x;
    const int warp = tid >> 5, lane = tid & 31;
    const int wm = warp >> 1, wn = warp & 1;
    const int m0 = blockIdx.y * 128, n0 = blockIdx.x * 128;

    float acc[4][8][4];
    #pragma unroll
    for (int f = 0; f < 4; ++f)
        #pragma unroll
        for (int n = 0; n < 8; ++n)
            #pragma unroll
            for (int k = 0; k < 4; ++k) acc[f][n][k] = 0.f;

    GEMM_MAINLOOP(D_DIM);

    float t = __ldg(tempPtr);
    float tau = (t > 20.f) ? t : log1pf(expf(t));   // softplus
    #pragma unroll
    for (int f = 0; f < 4; ++f)
        #pragma unroll
        for (int nf = 0; nf < 8; ++nf) {
            int row = m0 + wm * 64 + f * 16 + (lane >> 2);
            int col = n0 + wn * 64 + nf * 8 + (lane & 3) * 2;
            #pragma unroll
            for (int hh = 0; hh < 2; ++hh) {
                int r = row + hh * 8;
                float d0 = acc[f][nf][hh * 2 + 0];
                float d1 = acc[f][nf][hh * 2 + 1];
                float a0 = __expf(-tau * sqrtf(fmaxf(2.f - 2.f * d0, 0.f)));
                float a1 = __expf(-tau * sqrtf(fmaxf(2.f - 2.f * d1, 0.f)));
                *(__half2*)(outH + (size_t)r * P_DIM + col) =
                    __floats2half2_rn(a0, a1);
            }
        }
}

// ---------------------------------------------------------------------------
// GEMM2: logits[N,C] fp32 = act @ pct^T, f32 accum. PERSISTENT CTAs:
// grid = 296 (2 per SM); each CTA loops over the 1024 output tiles.
// Tile order: t>>3 = M tile, t&7 = N tile -> concurrent CTAs share A rows.
// ---------------------------------------------------------------------------
#define G2_TILES ((N_ROWS / 128) * (C_PAD / 128))   // 1024

__global__ void __launch_bounds__(128, 2) gemm2_persistent_kernel(
    const __half* __restrict__ A, const __half* __restrict__ B,
    float* __restrict__ outF)
{
    extern __shared__ __half sm[];
    const int tid  = threadIdx.x;
    const int warp = tid >> 5, lane = tid & 31;
    const int wm = warp >> 1, wn = warp & 1;

    for (int t = blockIdx.x; t < G2_TILES; t += gridDim.x) {
        const int m0 = (t >> 3) * 128;
        const int n0 = (t & 7) * 128;

        float acc[4][8][4];
        #pragma unroll
        for (int f = 0; f < 4; ++f)
            #pragma unroll
            for (int n = 0; n < 8; ++n)
                #pragma unroll
                for (int k = 0; k < 4; ++k) acc[f][n][k] = 0.f;

        GEMM_MAINLOOP(P_DIM);

        #pragma unroll
        for (int f = 0; f < 4; ++f)
            #pragma unroll
            for (int nf = 0; nf < 8; ++nf) {
                int row = m0 + wm * 64 + f * 16 + (lane >> 2);
                int col = n0 + wn * 64 + nf * 8 + (lane & 3) * 2;
                if (col < C_DIM) {   // even cols; pair never straddles C_DIM
                    #pragma unroll
                    for (int hh = 0; hh < 2; ++hh) {
                        int r = row + hh * 8;
                        float2 v = make_float2(acc[f][nf][hh * 2 + 0],
                                               acc[f][nf][hh * 2 + 1]);
                        *(float2*)(outF + (size_t)r * C_DIM + col) = v;
                    }
                }
            }
    }
}

// ---------------------------------------------------------------------------
// kernel_launch: 4 launches, all graph-capturable, no allocations.
// ---------------------------------------------------------------------------
extern "C" void kernel_launch(void* const* d_in, const int* in_sizes, int n_in,
                              void* d_out, int out_size) {
    const float* h    = (const float*)d_in[0];
    const float* prot = (const float*)d_in[1];
    const float* pc   = (const float*)d_in[2];
    const float* temp = (const float*)d_in[3];
    float* out = (float*)d_out;

    __half *hn = nullptr, *pn = nullptr, *act = nullptr, *pct = nullptr;
    cudaGetSymbolAddress((void**)&hn,  g_hn);
    cudaGetSymbolAddress((void**)&pn,  g_pn);
    cudaGetSymbolAddress((void**)&act, g_act);
    cudaGetSymbolAddress((void**)&pct, g_pct);

    cudaFuncSetAttribute(gemm_act_kernel,
                         cudaFuncAttributeMaxDynamicSharedMemorySize,
                         (int)GEMM_SMEM_BYTES);
    cudaFuncSetAttribute(gemm2_persistent_kernel,
                         cudaFuncAttributeMaxDynamicSharedMemorySize,
                         (int)GEMM_SMEM_BYTES);

    // 1) normalize h and prototypes -> fp16 (single launch, vectorized)
    normalize_rows_kernel<<<N_ROWS + P_DIM, 256>>>(h, prot);
    // 2) transpose + pad prototype_class -> fp16 [C_PAD, P]
    transpose_pc_kernel<<<dim3(P_DIM / 32, C_PAD / 32), dim3(32, 8)>>>(pc);
    // 3) GEMM1 (f32 accum) + dist/exp epilogue -> activations fp16 [N, P]
    gemm_act_kernel
        <<<dim3(P_DIM / 128, N_ROWS / 128), 128, GEMM_SMEM_BYTES>>>(
            hn, pn, act, temp);
    // 4) GEMM2 (f32 accum, persistent) -> logits fp32 [N, C]
    gemm2_persistent_kernel<<<296, 128, GEMM_SMEM_BYTES>>>(act, pct, out);
}

// round 9
// speedup vs baseline: 1.2094x; 1.0641x over previous
#include <cuda_runtime.h>
#include <cuda_fp16.h>
#include <cstdint>

// Problem dims (fixed by setup_inputs)
#define N_ROWS 16384
#define D_DIM  768
#define P_DIM  2048
#define C_DIM  1000
#define C_PAD  1024

// Scratch (allocation-free: __device__ globals)
__device__ __half g_hn[(size_t)N_ROWS * D_DIM];   // normalized h, fp16
__device__ __half g_pn[(size_t)P_DIM  * D_DIM];   // normalized prototypes, fp16
__device__ __half g_act[(size_t)N_ROWS * P_DIM];  // activations, fp16
__device__ __half g_pct[(size_t)C_PAD  * P_DIM];  // prototype_class transposed+padded

// ---------------------------------------------------------------------------
// Row L2 normalize (vectorized): one block per row, fp32 in -> fp16 out.
// ---------------------------------------------------------------------------
__global__ void normalize_rows_kernel(const float* __restrict__ xh,
                                      const float* __restrict__ xp) {
    int row = blockIdx.x;
    const float* xr;
    __half* yr;
    if (row < N_ROWS) {
        xr = xh + (size_t)row * D_DIM;
        yr = g_hn + (size_t)row * D_DIM;
    } else {
        xr = xp + (size_t)(row - N_ROWS) * D_DIM;
        yr = g_pn + (size_t)(row - N_ROWS) * D_DIM;
    }
    int tid = threadIdx.x;
    float4 v = make_float4(0.f, 0.f, 0.f, 0.f);
    if (tid < 192) v = ((const float4*)xr)[tid];
    float ss = v.x * v.x + v.y * v.y + v.z * v.z + v.w * v.w;
    #pragma unroll
    for (int o = 16; o; o >>= 1) ss += __shfl_xor_sync(0xffffffff, ss, o);
    __shared__ float wsum[8];
    int w = tid >> 5, l = tid & 31;
    if (l == 0) wsum[w] = ss;
    __syncthreads();
    if (w == 0) {
        float s = (l < 8) ? wsum[l] : 0.f;
        #pragma unroll
        for (int o = 4; o; o >>= 1) s += __shfl_xor_sync(0xffffffff, s, o);
        if (l == 0) wsum[0] = s;
    }
    __syncthreads();
    float inv = 1.0f / fmaxf(sqrtf(wsum[0]), 1e-12f);
    if (tid < 192) {
        __half2 h0 = __floats2half2_rn(v.x * inv, v.y * inv);
        __half2 h1 = __floats2half2_rn(v.z * inv, v.w * inv);
        uint2 pack;
        pack.x = *(uint32_t*)&h0;
        pack.y = *(uint32_t*)&h1;
        ((uint2*)yr)[tid] = pack;
    }
}

// ---------------------------------------------------------------------------
// Transpose prototype_class [P, C] fp32 -> g_pct [C_PAD, P] fp16, zero-padded
// ---------------------------------------------------------------------------
__global__ void transpose_pc_kernel(const float* __restrict__ pc) {
    __shared__ float tile[32][33];
    int p0 = blockIdx.x * 32, c0 = blockIdx.y * 32;
    int tx = threadIdx.x, ty = threadIdx.y;   // block (32, 8)
    #pragma unroll
    for (int j = 0; j < 32; j += 8) {
        int p = p0 + ty + j, c = c0 + tx;
        tile[ty + j][tx] = (c < C_DIM) ? pc[(size_t)p * C_DIM + c] : 0.f;
    }
    __syncthreads();
    #pragma unroll
    for (int j = 0; j < 32; j += 8) {
        int c = c0 + ty + j, p = p0 + tx;
        g_pct[(size_t)c * P_DIM + p] = __float2half(tile[tx][ty + j]);
    }
}

// ---------------------------------------------------------------------------
// GEMM scaffolding: CTA tile 128x128x32, 128 threads (2x2 warps),
// warp tile 64x64. Stage = A(128x32) + B(128x32), rows padded to 40 halfs.
// ---------------------------------------------------------------------------
#define PADK 40
#define STAGE_HALFS (2 * 128 * PADK)
#define G1_STAGES 3
#define G2_STAGES 4
#define G1_SMEM (G1_STAGES * STAGE_HALFS * sizeof(__half))   // 61440
#define G2_SMEM (G2_STAGES * STAGE_HALFS * sizeof(__half))   // 81920

__device__ __forceinline__ uint32_t smem_u32(const void* p) {
    return (uint32_t)__cvta_generic_to_shared(p);
}

// Load one K-chunk (32) of A rows [gm,gm+128) and B rows [gn,gn+128) -> stage s
#define LOAD_TILE(gm, gn, kt, s)                                              \
    do {                                                                      \
        const __half* ga = A + (size_t)(gm) * KDIM + (kt) * 32;               \
        const __half* gb = B + (size_t)(gn) * KDIM + (kt) * 32;               \
        __half* sa = sm + (size_t)(s) * STAGE_HALFS;                          \
        __half* sb = sa + 128 * PADK;                                         \
        _Pragma("unroll")                                                     \
        for (int i = 0; i < 4; ++i) {                                         \
            int l = tid + i * 128;                                            \
            int row = l >> 2, ch = l & 3;                                     \
            asm volatile("cp.async.cg.shared.global [%0], [%1], 16;\n"        \
                :: "r"(smem_u32(sa + row * PADK + ch * 8)),                   \
                   "l"(ga + (size_t)row * KDIM + ch * 8));                    \
            asm volatile("cp.async.cg.shared.global [%0], [%1], 16;\n"        \
                :: "r"(smem_u32(sb + row * PADK + ch * 8)),                   \
                   "l"(gb + (size_t)row * KDIM + ch * 8));                    \
        }                                                                     \
    } while (0)

#define LDSM_A(r, sa, f, ks)                                                  \
    do {                                                                      \
        int row_ = wm * 64 + (f) * 16 + (lane & 15);                          \
        int col_ = (ks) * 16 + (lane >> 4) * 8;                               \
        asm volatile(                                                         \
            "ldmatrix.sync.aligned.m8n8.x4.shared.b16 {%0,%1,%2,%3}, [%4];\n" \
            : "=r"((r)[0]), "=r"((r)[1]), "=r"((r)[2]), "=r"((r)[3])          \
            : "r"(smem_u32((sa) + row_ * PADK + col_)));                      \
    } while (0)

#define LDSM_B(r, sb, p, ks)                                                  \
    do {                                                                      \
        int row_ = wn * 64 + (p) * 16 + (lane & 7) + ((lane >> 4) << 3);      \
        int col_ = (ks) * 16 + ((lane >> 3) & 1) * 8;                         \
        asm volatile(                                                         \
            "ldmatrix.sync.aligned.m8n8.x4.shared.b16 {%0,%1,%2,%3}, [%4];\n" \
            : "=r"((r)[0]), "=r"((r)[1]), "=r"((r)[2]), "=r"((r)[3])          \
            : "r"(smem_u32((sb) + row_ * PADK + col_)));                      \
    } while (0)

#define HMMA_F32(c, a4, b0, b1)                                               \
    asm volatile(                                                             \
        "mma.sync.aligned.m16n8k16.row.col.f32.f16.f16.f32 "                  \
        "{%0,%1,%2,%3},{%4,%5,%6,%7},{%8,%9},{%0,%1,%2,%3};\n"                \
        : "+f"((c)[0]), "+f"((c)[1]), "+f"((c)[2]), "+f"((c)[3])              \
        : "r"((a4)[0]), "r"((a4)[1]), "r"((a4)[2]), "r"((a4)[3]),             \
          "r"(b0), "r"(b1))

#define HMMA_F16(c, a4, b0, b1)                                               \
    asm volatile(                                                             \
        "mma.sync.aligned.m16n8k16.row.col.f16.f16.f16.f16 "                  \
        "{%0,%1},{%2,%3,%4,%5},{%6,%7},{%0,%1};\n"                            \
        : "+r"((c)[0]), "+r"((c)[1])                                          \
        : "r"((a4)[0]), "r"((a4)[1]), "r"((a4)[2]), "r"((a4)[3]),             \
          "r"(b0), "r"(b1))

// ---------------------------------------------------------------------------
// GEMM1: f16 accumulators, 3 stages, 3 CTAs/SM (register/smem balanced for
// 12 warps/SM -> 3 warps/SMSP stagger over LDSM/barrier windows).
// act[N,P] fp16 = exp(-tau*sqrt(max(2-2*dot, 0)))
// ---------------------------------------------------------------------------
__global__ void __launch_bounds__(128, 3) gemm_act_kernel(
    const __half* __restrict__ A, const __half* __restrict__ B,
    __half* __restrict__ outH, const float* __restrict__ tempPtr)
{
    constexpr int KDIM = D_DIM;
    constexpr int KT = KDIM / 32;   // 24
    extern __shared__ __half sm[];
    const int tid  = threadIdx.x;
    const int warp = tid >> 5, lane = tid & 31;
    const int wm = warp >> 1, wn = warp & 1;
    const int m0 = blockIdx.y * 128, n0 = blockIdx.x * 128;

    uint32_t acc[4][8][2];
    #pragma unroll
    for (int f = 0; f < 4; ++f)
        #pragma unroll
        for (int n = 0; n < 8; ++n) { acc[f][n][0] = 0u; acc[f][n][1] = 0u; }

    #pragma unroll
    for (int s = 0; s < G1_STAGES - 1; ++s) {
        LOAD_TILE(m0, n0, s, s);
        asm volatile("cp.async.commit_group;\n");
    }

    for (int kt = 0; kt < KT; ++kt) {
        asm volatile("cp.async.wait_group %0;\n" :: "n"(G1_STAGES - 2));
        __syncthreads();
        const int cur = kt % G1_STAGES;
        const int nxt = kt + G1_STAGES - 1;
        if (nxt < KT) LOAD_TILE(m0, n0, nxt, nxt % G1_STAGES);
        asm volatile("cp.async.commit_group;\n");

        const __half* sa = sm + (size_t)cur * STAGE_HALFS;
        const __half* sb = sa + 128 * PADK;
        #pragma unroll
        for (int ks = 0; ks < 2; ++ks) {
            uint32_t a[4][4], b[4][4];
            #pragma unroll
            for (int f = 0; f < 4; ++f) LDSM_A(a[f], sa, f, ks);
            #pragma unroll
            for (int p = 0; p < 4; ++p) LDSM_B(b[p], sb, p, ks);
            #pragma unroll
            for (int f = 0; f < 4; ++f)
                #pragma unroll
                for (int nf = 0; nf < 8; ++nf)
                    HMMA_F16(acc[f][nf], a[f],
                             b[nf >> 1][(nf & 1) * 2 + 0],
                             b[nf >> 1][(nf & 1) * 2 + 1]);
        }
    }

    float t = __ldg(tempPtr);
    float tau = (t > 20.f) ? t : log1pf(expf(t));   // softplus
    #pragma unroll
    for (int f = 0; f < 4; ++f)
        #pragma unroll
        for (int nf = 0; nf < 8; ++nf) {
            int row = m0 + wm * 64 + f * 16 + (lane >> 2);
            int col = n0 + wn * 64 + nf * 8 + (lane & 3) * 2;
            #pragma unroll
            for (int hh = 0; hh < 2; ++hh) {
                int r = row + hh * 8;
                float2 d = __half22float2(*(__half2*)&acc[f][nf][hh]);
                float a0 = __expf(-tau * sqrtf(fmaxf(2.f - 2.f * d.x, 0.f)));
                float a1 = __expf(-tau * sqrtf(fmaxf(2.f - 2.f * d.y, 0.f)));
                *(__half2*)(outH + (size_t)r * P_DIM + col) =
                    __floats2half2_rn(a0, a1);
            }
        }
}

// ---------------------------------------------------------------------------
// GEMM2: f32 accum, persistent CTAs with CROSS-TILE rolling prefetch: stage
// rotation continues across tiles so the next tile's first 3 chunks are in
// flight during the current epilogue (no per-tile prologue bubble).
// ---------------------------------------------------------------------------
#define G2_TILES ((N_ROWS / 128) * (C_PAD / 128))   // 1024

__global__ void __launch_bounds__(128, 2) gemm2_persistent_kernel(
    const __half* __restrict__ A, const __half* __restrict__ B,
    float* __restrict__ outF)
{
    constexpr int KDIM = P_DIM;
    constexpr int KT = KDIM / 32;   // 64 (divisible by G2_STAGES)
    extern __shared__ __half sm[];
    const int tid  = threadIdx.x;
    const int warp = tid >> 5, lane = tid & 31;
    const int wm = warp >> 1, wn = warp & 1;

    const int t0 = blockIdx.x;
    if (t0 < G2_TILES) {
        int m0 = (t0 >> 3) * 128, n0 = (t0 & 7) * 128;
        #pragma unroll
        for (int s = 0; s < G2_STAGES - 1; ++s) {
            LOAD_TILE(m0, n0, s, s);
            asm volatile("cp.async.commit_group;\n");
        }
    }

    for (int t = t0; t < G2_TILES; t += gridDim.x) {
        const int m0 = (t >> 3) * 128, n0 = (t & 7) * 128;
        const int tn = t + gridDim.x;
        const bool hasn = tn < G2_TILES;
        const int m0n = hasn ? (tn >> 3) * 128 : 0;
        const int n0n = hasn ? (tn & 7) * 128 : 0;

        float acc[4][8][4];
        #pragma unroll
        for (int f = 0; f < 4; ++f)
            #pragma unroll
            for (int n = 0; n < 8; ++n)
                #pragma unroll
                for (int k = 0; k < 4; ++k) acc[f][n][k] = 0.f;

        for (int kt = 0; kt < KT; ++kt) {
            asm volatile("cp.async.wait_group %0;\n" :: "n"(G2_STAGES - 2));
            __syncthreads();
            const int cur = kt & (G2_STAGES - 1);
            const int lk = kt + G2_STAGES - 1;
            if (lk < KT)       LOAD_TILE(m0, n0, lk, lk & (G2_STAGES - 1));
            else if (hasn)     LOAD_TILE(m0n, n0n, lk - KT, lk & (G2_STAGES - 1));
            asm volatile("cp.async.commit_group;\n");

            const __half* sa = sm + (size_t)cur * STAGE_HALFS;
            const __half* sb = sa + 128 * PADK;
            #pragma unroll
            for (int ks = 0; ks < 2; ++ks) {
                uint32_t a[4][4], b[4][4];
                #pragma unroll
                for (int f = 0; f < 4; ++f) LDSM_A(a[f], sa, f, ks);
                #pragma unroll
                for (int p = 0; p < 4; ++p) LDSM_B(b[p], sb, p, ks);
                #pragma unroll
                for (int f = 0; f < 4; ++f)
                    #pragma unroll
                    for (int nf = 0; nf < 8; ++nf)
                        HMMA_F32(acc[f][nf], a[f],
                                 b[nf >> 1][(nf & 1) * 2 + 0],
                                 b[nf >> 1][(nf & 1) * 2 + 1]);
            }
        }

        // Epilogue overlaps with next tile's in-flight prologue loads.
        #pragma unroll
        for (int f = 0; f < 4; ++f)
            #pragma unroll
            for (int nf = 0; nf < 8; ++nf) {
                int row = m0 + wm * 64 + f * 16 + (lane >> 2);
                int col = n0 + wn * 64 + nf * 8 + (lane & 3) * 2;
                if (col < C_DIM) {   // even cols; pair never straddles C_DIM
                    #pragma unroll
                    for (int hh = 0; hh < 2; ++hh) {
                        int r = row + hh * 8;
                        float2 v = make_float2(acc[f][nf][hh * 2 + 0],
                                               acc[f][nf][hh * 2 + 1]);
                        *(float2*)(outF + (size_t)r * C_DIM + col) = v;
                    }
                }
            }
    }
}

// ---------------------------------------------------------------------------
// kernel_launch: 4 launches, all graph-capturable, no allocations.
// ---------------------------------------------------------------------------
extern "C" void kernel_launch(void* const* d_in, const int* in_sizes, int n_in,
                              void* d_out, int out_size) {
    const float* h    = (const float*)d_in[0];
    const float* prot = (const float*)d_in[1];
    const float* pc   = (const float*)d_in[2];
    const float* temp = (const float*)d_in[3];
    float* out = (float*)d_out;

    __half *hn = nullptr, *pn = nullptr, *act = nullptr, *pct = nullptr;
    cudaGetSymbolAddress((void**)&hn,  g_hn);
    cudaGetSymbolAddress((void**)&pn,  g_pn);
    cudaGetSymbolAddress((void**)&act, g_act);
    cudaGetSymbolAddress((void**)&pct, g_pct);

    cudaFuncSetAttribute(gemm_act_kernel,
                         cudaFuncAttributeMaxDynamicSharedMemorySize,
                         (int)G1_SMEM);
    cudaFuncSetAttribute(gemm2_persistent_kernel,
                         cudaFuncAttributeMaxDynamicSharedMemorySize,
                         (int)G2_SMEM);

    // 1) normalize h and prototypes -> fp16 (single launch, vectorized)
    normalize_rows_kernel<<<N_ROWS + P_DIM, 256>>>(h, prot);
    // 2) transpose + pad prototype_class -> fp16 [C_PAD, P]
    transpose_pc_kernel<<<dim3(P_DIM / 32, C_PAD / 32), dim3(32, 8)>>>(pc);
    // 3) GEMM1 (f16 accum, 3 CTAs/SM) + dist/exp epilogue -> act fp16 [N, P]
    gemm_act_kernel
        <<<dim3(P_DIM / 128, N_ROWS / 128), 128, G1_SMEM>>>(hn, pn, act, temp);
    // 4) GEMM2 (f32 accum, persistent + rolling prefetch) -> logits fp32
    gemm2_persistent_kernel<<<296, 128, G2_SMEM>>>(act, pct, out);
}